// round 4
// baseline (speedup 1.0000x reference)
#include <cuda_runtime.h>

// Problem constants (match reference setup_inputs)
#define BQ 8
#define CC 64
#define HH 512
#define WW 512
#define OO 64
#define SS 4
// hs = ws = 128; elements per pooled tile = 128*128 = 16384

// Scratch (allocation-free rule: __device__ globals)
__device__ float g_pooled[BQ * CC * SS * SS];    // [b, c, i, j]
__device__ float g_weighted[BQ * OO * SS * SS];  // [b, o, i, j]

// ---------------------------------------------------------------------------
// Kernel 1: segment mean-pool, ONE CTA PER (b,c) PLANE.
// Grid: 512 CTAs x 256 threads -> fully resident in a single wave (no
// wave-quantization tail). Each CTA streams a 512x512 plane (1 MB) and
// produces all 16 tile sums.
// Thread layout: col4 = tid & 127 (constant -> j = col4>>5 constant per
// warp), row parity roff = tid>>7; threads cover 2 rows per iteration.
// Per-thread: 4 segments x 64 row-iters = 256 float4 streaming loads.
// ---------------------------------------------------------------------------
__global__ __launch_bounds__(256) void pool_kernel(const float* __restrict__ x) {
    int bc  = blockIdx.x;            // b*CC + c
    int tid = threadIdx.x;
    int col4 = tid & 127;
    int roff = tid >> 7;             // 0 or 1

    const float4* base = reinterpret_cast<const float4*>(x) +
                         (size_t)bc * (HH * (WW / 4)) + col4;

    float s[SS];
    #pragma unroll
    for (int i = 0; i < SS; i++) {
        float acc = 0.0f;
        const float4* seg = base + (size_t)(i * 128 + roff) * 128;
        #pragma unroll 8
        for (int r = 0; r < 64; r++) {
            float4 v = __ldcs(&seg[(size_t)r * 256]);   // +2 rows per iter
            acc += (v.x + v.y) + (v.z + v.w);
        }
        s[i] = acc;
    }

    // warp reduce each segment sum (all lanes in a warp share the same j)
    #pragma unroll
    for (int i = 0; i < SS; i++) {
        #pragma unroll
        for (int off = 16; off; off >>= 1)
            s[i] += __shfl_down_sync(0xffffffffu, s[i], off);
    }

    __shared__ float sj[SS * SS];    // [i][j]
    if (tid < SS * SS) sj[tid] = 0.0f;
    __syncthreads();

    int j = (tid >> 5) & 3;          // warp's column segment
    if ((tid & 31) == 0) {
        #pragma unroll
        for (int i = 0; i < SS; i++)
            atomicAdd(&sj[i * SS + j], s[i]);
    }
    __syncthreads();

    if (tid < SS * SS)
        g_pooled[(size_t)bc * (SS * SS) + tid] = sj[tid] * (1.0f / 16384.0f);
}

// ---------------------------------------------------------------------------
// Kernel 2: per-tile linear + bias + seg_w. ~3 us, negligible.
// Grid: BQ*SS*SS CTAs of OO threads; CTA handles one (b, i, j) tile.
// ---------------------------------------------------------------------------
__global__ __launch_bounds__(OO) void mix_kernel(const float* __restrict__ Wm,
                                                 const float* __restrict__ bias,
                                                 const float* __restrict__ seg_w) {
    int blk = blockIdx.x;            // b*16 + ij
    int ij  = blk & 15;
    int b   = blk >> 4;

    __shared__ float pool[CC];
    int o = threadIdx.x;
    pool[o] = g_pooled[(size_t)(b * CC + o) * (SS * SS) + ij];
    __syncthreads();

    float acc = 0.0f;
    const float* wrow = Wm + (size_t)o * CC;
    #pragma unroll
    for (int c = 0; c < CC; c++) acc += pool[c] * wrow[c];

    acc = (acc + bias[o]) * seg_w[ij];
    g_weighted[(size_t)(b * OO + o) * (SS * SS) + ij] = acc;
}

// ---------------------------------------------------------------------------
// Kernel 3: broadcast, ONE CTA PER (b,o) PLANE.
// Grid: 512 CTAs x 256 threads -> single wave, fully resident.
// Each CTA writes a 512x512 plane (1 MB). Thread's j is constant; the 4
// per-segment values live in registers. 256 float4 streaming stores/thread.
// ---------------------------------------------------------------------------
__global__ __launch_bounds__(256) void bcast_kernel(float4* __restrict__ out) {
    int p   = blockIdx.x;            // b*OO + o
    int tid = threadIdx.x;
    int col4 = tid & 127;
    int roff = tid >> 7;
    int j    = col4 >> 5;            // constant per thread

    __shared__ float wv[SS * SS];
    if (tid < SS * SS) wv[tid] = g_weighted[(size_t)p * (SS * SS) + tid];
    __syncthreads();

    float4 vv[SS];
    #pragma unroll
    for (int i = 0; i < SS; i++) {
        float v = wv[i * SS + j];
        vv[i] = make_float4(v, v, v, v);
    }

    float4* base = out + (size_t)p * (HH * (WW / 4)) + col4;
    #pragma unroll
    for (int i = 0; i < SS; i++) {
        float4* seg = base + (size_t)(i * 128 + roff) * 128;
        #pragma unroll 8
        for (int r = 0; r < 64; r++)
            __stcs(&seg[(size_t)r * 256], vv[i]);   // +2 rows per iter
    }
}

// ---------------------------------------------------------------------------
extern "C" void kernel_launch(void* const* d_in, const int* in_sizes, int n_in,
                              void* d_out, int out_size) {
    const float* x     = (const float*)d_in[0];   // [B, C, H, W]
    const float* Wm    = (const float*)d_in[1];   // [O, C]
    const float* bias  = (const float*)d_in[2];   // [O]
    const float* seg_w = (const float*)d_in[3];   // [S, S]
    float* out = (float*)d_out;                   // [B, O, H, W]

    pool_kernel<<<BQ * CC, 256>>>(x);
    mix_kernel<<<BQ * SS * SS, OO>>>(Wm, bias, seg_w);
    bcast_kernel<<<BQ * OO, 256>>>((float4*)out);
}

// round 5
// speedup vs baseline: 1.0661x; 1.0661x over previous
#include <cuda_runtime.h>

// Problem constants (match reference setup_inputs)
#define BQ 8
#define CC 64
#define HH 512
#define WW 512
#define OO 64
#define SS 4
#define NPOOL (BQ * CC * SS)   // 2048 pool stripes  (b, c, i)
#define NBC   (BQ * OO * SS)   // 2048 bcast stripes (b, o, i)
#define GRID  1184             // 8 CTAs/SM x 148 SMs -> guaranteed co-resident

// Scratch (allocation-free rule: __device__ globals)
__device__ float g_pooled[BQ * SS * SS * CC];  // [b, i, j, c] (c-contiguous for warp dot)
__device__ int   g_done[BQ];                   // pool stripes completed per batch

// ---------------------------------------------------------------------------
// Reset: zero the per-batch flags before each fused run (graph-serialized).
// ---------------------------------------------------------------------------
__global__ void reset_kernel() {
    if (threadIdx.x < BQ) g_done[threadIdx.x] = 0;
}

// ---------------------------------------------------------------------------
// Fused persistent kernel.
// Phase 1 (pool): grid-stride over 2048 (b,c,i) stripes; each stripe streams
//   128 rows x 512 cols with __ldcs (R2's proven 87%-DRAM shape). Release a
//   per-batch counter after each stripe.
// Phase 2 (bcast): grid-stride over 2048 (b,o,i) stripes; acquire-spin until
//   batch b fully pooled, per-warp redundant 64-wide dot (no block sync in
//   the head), then stream 128 rows x 512 cols of stores with __stcs.
// Deadlock-free: pool work never waits; all GRID CTAs are co-resident
//   (launch_bounds(256,8) caps regs at 32 -> 8 CTAs/SM).
// ---------------------------------------------------------------------------
__global__ __launch_bounds__(256, 8) void fused_kernel(
    const float4* __restrict__ x4, float4* __restrict__ out,
    const float* __restrict__ Wm, const float* __restrict__ bias,
    const float* __restrict__ seg_w) {
    int tid = threadIdx.x;

    // ---------------- Phase 1: pool ----------------
    __shared__ float sj[SS];
    for (int s = blockIdx.x; s < NPOOL; s += GRID) {
        int b = s >> 8, c = (s >> 2) & 63, i = s & 3;
        const float4* base = x4 + ((size_t)(b * CC + c) * HH + (size_t)i * 128) * (WW / 4);

        float sum = 0.0f;
        #pragma unroll 8
        for (int idx = tid; idx < 128 * 128; idx += 256) {
            float4 v = __ldcs(&base[idx]);        // col4 = tid&127 const -> warp j const
            sum += (v.x + v.y) + (v.z + v.w);
        }
        #pragma unroll
        for (int off = 16; off; off >>= 1)
            sum += __shfl_down_sync(0xffffffffu, sum, off);

        if (tid < SS) sj[tid] = 0.0f;
        __syncthreads();
        if ((tid & 31) == 0) atomicAdd(&sj[(tid >> 5) & 3], sum);
        __syncthreads();
        if (tid < SS)
            g_pooled[((size_t)(b * SS + i) * SS + tid) * CC + c] = sj[tid] * (1.0f / 16384.0f);
        __syncthreads();                           // tile stores visible block-wide
        if (tid == 0) {
            __threadfence();                       // release g_pooled stores
            atomicAdd(&g_done[b], 1);
        }
        __syncthreads();                           // sj reuse safety
    }

    // ---------------- Phase 2: bcast ----------------
    for (int t = blockIdx.x; t < NBC; t += GRID) {
        int b = t >> 8, o = (t >> 2) & 63, i = t & 3;

        if (tid == 0) {                            // acquire-spin until batch pooled
            int d;
            do {
                asm volatile("ld.acquire.gpu.s32 %0, [%1];" : "=r"(d) : "l"(&g_done[b]));
                if (d < CC * SS) __nanosleep(200);
            } while (d < CC * SS);
        }
        __syncthreads();                           // extend acquire to the block

        // per-warp redundant dot (no block sync -> overlaps other warps' stores)
        int lane = tid & 31;
        const float* pb = &g_pooled[(size_t)(b * SS + i) * SS * CC];
        float w0 = __ldg(&Wm[(size_t)o * CC + lane]);
        float w1 = __ldg(&Wm[(size_t)o * CC + lane + 32]);
        float acc[SS];
        #pragma unroll
        for (int j = 0; j < SS; j++) {
            acc[j] = pb[(size_t)j * CC + lane] * w0 + pb[(size_t)j * CC + lane + 32] * w1;
            #pragma unroll
            for (int off = 16; off; off >>= 1)
                acc[j] += __shfl_xor_sync(0xffffffffu, acc[j], off);
        }
        int j = (tid & 127) >> 5;                  // thread's column segment (const)
        float v = (acc[j] + __ldg(&bias[o])) * __ldg(&seg_w[i * SS + j]);
        float4 v4 = make_float4(v, v, v, v);

        float4* dst = out + ((size_t)(b * OO + o) * HH + (size_t)i * 128) * (WW / 4) + tid;
        #pragma unroll 8
        for (int k = 0; k < 64; k++)
            __stcs(&dst[(size_t)k * 256], v4);     // 2 rows per iter, fully coalesced
    }
}

// ---------------------------------------------------------------------------
extern "C" void kernel_launch(void* const* d_in, const int* in_sizes, int n_in,
                              void* d_out, int out_size) {
    const float* x     = (const float*)d_in[0];   // [B, C, H, W]
    const float* Wm    = (const float*)d_in[1];   // [O, C]
    const float* bias  = (const float*)d_in[2];   // [O]
    const float* seg_w = (const float*)d_in[3];   // [S, S]
    float* out = (float*)d_out;                   // [B, O, H, W]

    reset_kernel<<<1, 32>>>();
    fused_kernel<<<GRID, 256>>>((const float4*)x, (float4*)out, Wm, bias, seg_w);
}

// round 6
// speedup vs baseline: 1.0788x; 1.0120x over previous
#include <cuda_runtime.h>

// Problem constants (match reference setup_inputs)
#define BQ 8
#define CC 64
#define HH 512
#define WW 512
#define OO 64
#define SS 4
#define NPOOL (BQ * CC * SS)   // 2048 pool stripes  (b, c, i)
#define NBC   (BQ * OO * SS)   // 2048 bcast stripes (b, o, i)
#define GRID  1024             // 2048 % GRID == 0 -> exactly 2+2 stripes per CTA;
                               // <=1184 co-residency cap (8/SM x 148 SMs) -> no deadlock

// Scratch (allocation-free rule: __device__ globals; zero-init at module load)
__device__ float g_pooled[BQ * SS * SS * CC];  // [b, i, j, c] (c-contiguous for warp dot)
__device__ int   g_done[BQ];                   // pool stripes completed per batch (0..256)
__device__ int   g_cons[BQ];                   // bcast stripes completed per batch (0..256)

// ---------------------------------------------------------------------------
// Single fused persistent kernel (single graph node — no reset kernel).
//
// Phase 1 (pool): grid-stride over 2048 (b,c,i) stripes; each streams
//   128 rows x 512 cols with __ldcs. Release: fence + atomicAdd g_done[b].
// Phase 2 (bcast): acquire-spin until g_done[b]==256, per-warp redundant
//   64-wide dot (no block sync in head), stream stores with __stcs.
//
// Self-reset: each consumer stripe bumps g_cons[b]; the 256th consumer of
//   batch b zeroes g_done[b] and g_cons[b]. All waits on batch b have
//   already passed at that point (every consumer increments only after its
//   own wait), so the reset races with nothing; the kernel boundary
//   publishes the zeros to the next graph replay.
// Deadlock-free: pool work never waits; all GRID CTAs co-resident
//   (launch_bounds(256,8) caps regs at 32 -> 8 CTAs/SM).
// ---------------------------------------------------------------------------
__global__ __launch_bounds__(256, 8) void fused_kernel(
    const float4* __restrict__ x4, float4* __restrict__ out,
    const float* __restrict__ Wm, const float* __restrict__ bias,
    const float* __restrict__ seg_w) {
    int tid = threadIdx.x;

    // ---------------- Phase 1: pool ----------------
    __shared__ float sj[SS];
    #pragma unroll
    for (int u = 0; u < NPOOL / GRID; u++) {
        int s = blockIdx.x + u * GRID;
        int b = s >> 8, c = (s >> 2) & 63, i = s & 3;
        const float4* base = x4 + ((size_t)(b * CC + c) * HH + (size_t)i * 128) * (WW / 4);

        float sum = 0.0f;
        #pragma unroll 8
        for (int idx = tid; idx < 128 * 128; idx += 256) {
            float4 v = __ldcs(&base[idx]);        // col4 = tid&127 const -> warp j const
            sum += (v.x + v.y) + (v.z + v.w);
        }
        #pragma unroll
        for (int off = 16; off; off >>= 1)
            sum += __shfl_down_sync(0xffffffffu, sum, off);

        if (tid < SS) sj[tid] = 0.0f;
        __syncthreads();
        if ((tid & 31) == 0) atomicAdd(&sj[(tid >> 5) & 3], sum);
        __syncthreads();
        if (tid < SS)
            g_pooled[((size_t)(b * SS + i) * SS + tid) * CC + c] = sj[tid] * (1.0f / 16384.0f);
        if (tid == 0) {
            __threadfence();                       // release g_pooled stores
            atomicAdd(&g_done[b], 1);
        }
        __syncthreads();                           // sj reuse safety
    }

    // ---------------- Phase 2: bcast ----------------
    #pragma unroll
    for (int u = 0; u < NBC / GRID; u++) {
        int t = blockIdx.x + u * GRID;
        int b = t >> 8, o = (t >> 2) & 63, i = t & 3;

        if (tid == 0) {                            // acquire-spin until batch pooled
            int d;
            do {
                asm volatile("ld.acquire.gpu.s32 %0, [%1];" : "=r"(d) : "l"(&g_done[b]));
                if (d < CC * SS) __nanosleep(200);
            } while (d < CC * SS);
            // self-reset bookkeeping: last consumer of batch b clears counters
            int prev = atomicAdd(&g_cons[b], 1);
            if (prev == OO * SS - 1) {
                g_done[b] = 0;
                g_cons[b] = 0;
            }
        }
        __syncthreads();                           // extend acquire to the block

        // per-warp redundant dot (no block sync -> overlaps other warps' stores)
        int lane = tid & 31;
        const float* pb = &g_pooled[(size_t)(b * SS + i) * SS * CC];
        float w0 = __ldg(&Wm[(size_t)o * CC + lane]);
        float w1 = __ldg(&Wm[(size_t)o * CC + lane + 32]);
        float acc[SS];
        #pragma unroll
        for (int j = 0; j < SS; j++) {
            acc[j] = pb[(size_t)j * CC + lane] * w0 + pb[(size_t)j * CC + lane + 32] * w1;
            #pragma unroll
            for (int off = 16; off; off >>= 1)
                acc[j] += __shfl_xor_sync(0xffffffffu, acc[j], off);
        }
        int j = (tid & 127) >> 5;                  // thread's column segment (const)
        float v = (acc[j] + __ldg(&bias[o])) * __ldg(&seg_w[i * SS + j]);
        float4 v4 = make_float4(v, v, v, v);

        float4* dst = out + ((size_t)(b * OO + o) * HH + (size_t)i * 128) * (WW / 4) + tid;
        #pragma unroll 8
        for (int k = 0; k < 64; k++)
            __stcs(&dst[(size_t)k * 256], v4);     // 2 rows per iter, fully coalesced
    }
}

// ---------------------------------------------------------------------------
extern "C" void kernel_launch(void* const* d_in, const int* in_sizes, int n_in,
                              void* d_out, int out_size) {
    const float* x     = (const float*)d_in[0];   // [B, C, H, W]
    const float* Wm    = (const float*)d_in[1];   // [O, C]
    const float* bias  = (const float*)d_in[2];   // [O]
    const float* seg_w = (const float*)d_in[3];   // [S, S]
    float* out = (float*)d_out;                   // [B, O, H, W]

    fused_kernel<<<GRID, 256>>>((const float4*)x, (float4*)out, Wm, bias, seg_w);
}

// round 7
// speedup vs baseline: 1.1476x; 1.0638x over previous
#include <cuda_runtime.h>

// Problem constants (match reference setup_inputs)
#define BQ 8
#define CC 64
#define HH 512
#define WW 512
#define OO 64
#define SS 4
// hs = ws = 128; elements per pooled tile = 128*128 = 16384

// Scratch (allocation-free rule: __device__ global). 8 KB, L2-resident.
__device__ float g_pooled[BQ * SS * SS * CC];    // [b, i, j, c]  (c-contiguous)

// ---------------------------------------------------------------------------
// Kernel 1: segment mean-pool (exact R2 shape: 87% DRAM, 6.9 TB/s).
// Grid: BQ*CC*SS = 2048 CTAs; each CTA streams one (b, c, i) stripe
// = 128 rows x 512 cols with DEFAULT-policy float4 loads (ldcs measured
// worse on the read path). Thread's column (idx & 127) is invariant under
// the +=256 stride, so each warp sees exactly one j segment.
// ---------------------------------------------------------------------------
__global__ __launch_bounds__(256) void pool_kernel(const float* __restrict__ x) {
    int bi = blockIdx.x;             // b*CC*SS + c*SS + i
    int i  = bi % SS;
    int c  = (bi / SS) % CC;
    int b  = bi / (SS * CC);

    const float4* base = reinterpret_cast<const float4*>(
        x + (((size_t)(b * CC + c)) * HH + (size_t)i * 128) * WW);

    int tid = threadIdx.x;
    float sum = 0.0f;
    // 128 rows * 128 float4/row = 16384 float4 per stripe
    #pragma unroll 8
    for (int idx = tid; idx < 128 * 128; idx += 256) {
        float4 v = base[idx];        // row*128 + col4 == idx
        sum += (v.x + v.y) + (v.z + v.w);
    }

    // warp reduce (all lanes in a warp share the same j)
    #pragma unroll
    for (int off = 16; off; off >>= 1)
        sum += __shfl_down_sync(0xffffffffu, sum, off);

    __shared__ float sj[SS];
    if (tid < SS) sj[tid] = 0.0f;
    __syncthreads();

    if ((tid & 31) == 0) atomicAdd(&sj[(tid >> 5) & 3], sum);
    __syncthreads();

    if (tid < SS)                    // layout [b][i][j][c]: c-contiguous for the dot head
        g_pooled[((size_t)(b * SS + i) * SS + tid) * CC + c] =
            sj[tid] * (1.0f / 16384.0f);
}

// ---------------------------------------------------------------------------
// Kernel 2 (bcast + fused mix): exact R2 store shape (16384 CTAs, 8 plain
// float4 stores per thread) with a SYNC-FREE warp-redundant dot head.
// Each warp has a single (b,o,i,j); lanes load 2 pooled + 2 W values
// (all L2-resident: 8 KB + 16 KB), fma, 5-step xor-butterfly -> every lane
// holds the tile value. No shared memory, no barrier: the ~200-cycle head
// hides under the other 7 warps' / other CTAs' store streams.
// ---------------------------------------------------------------------------
__global__ __launch_bounds__(256) void bcast_kernel(float4* __restrict__ out,
                                                    const float* __restrict__ Wm,
                                                    const float* __restrict__ bias,
                                                    const float* __restrict__ seg_w) {
    size_t gbase = (size_t)blockIdx.x * 2048;     // f4 index of CTA start
    size_t r0    = gbase >> 7;                    // starting row (global)
    int    h0    = (int)(r0 & (HH - 1));          // row within plane
    size_t p     = r0 >> 9;                       // plane = b*OO + o
    int    i     = h0 >> 7;                       // row segment (const per CTA)
    int    o     = (int)(p & (OO - 1));
    int    b     = (int)(p >> 6);

    int tid  = threadIdx.x;
    int lane = tid & 31;
    int j    = (tid & 127) >> 5;                  // column segment (const per warp)

    // --- warp-redundant dot head (no syncs) ---
    const float* pb = &g_pooled[((size_t)(b * SS + i) * SS + j) * CC];
    float acc = pb[lane]      * __ldg(&Wm[(size_t)o * CC + lane]) +
                pb[lane + 32] * __ldg(&Wm[(size_t)o * CC + lane + 32]);
    #pragma unroll
    for (int off = 16; off; off >>= 1)
        acc += __shfl_xor_sync(0xffffffffu, acc, off);

    float v = (acc + __ldg(&bias[o])) * __ldg(&seg_w[i * SS + j]);
    float4 v4 = make_float4(v, v, v, v);

    // --- store body: 16 rows of one (b,o) plane, fully coalesced ---
    float4* dst = out + gbase + tid;
    #pragma unroll
    for (int k = 0; k < 8; k++)
        dst[(size_t)k * 256] = v4;
}

// ---------------------------------------------------------------------------
extern "C" void kernel_launch(void* const* d_in, const int* in_sizes, int n_in,
                              void* d_out, int out_size) {
    const float* x     = (const float*)d_in[0];   // [B, C, H, W]
    const float* Wm    = (const float*)d_in[1];   // [O, C]
    const float* bias  = (const float*)d_in[2];   // [O]
    const float* seg_w = (const float*)d_in[3];   // [S, S]
    float* out = (float*)d_out;                   // [B, O, H, W]

    pool_kernel<<<BQ * CC * SS, 256>>>(x);

    // total float4 in output = 8*64*512*512/4 = 33554432; 2048 f4 per CTA
    int bcast_blocks = (BQ * OO * HH * WW / 4) / 2048;  // 16384
    bcast_kernel<<<bcast_blocks, 256>>>((float4*)out, Wm, bias, seg_w);
}